// round 2
// baseline (speedup 1.0000x reference)
#include <cuda_runtime.h>

#define BATCH 4096
#define LSQ   64
#define HID   64
#define GATES 256
#define NFLD  11
#define LN    32

// ---------------- scratch (no allocations allowed) ----------------
__device__ float g_xe[85 * 256];            // base_emb @ seq_Wx, per token value
__device__ float g_m[2 * BATCH * HID];      // [from rows 0..4095 | to rows 4096..8191] x 64
__device__ float g_nwf[NFLD * BATCH * 8];   // [11][4096][8]

__constant__ int c_fm[11] = {0, 0, 1, 1, 2, 2, 3, 3, 4, 5, 5};

__device__ __forceinline__ float sigf(float x) { return 1.0f / (1.0f + __expf(-x)); }
__device__ __forceinline__ float tanhf_fast(float x) { return 2.0f / (1.0f + __expf(-2.0f * x)) - 1.0f; }

// ---------------- kernel 1: xe[v][j] = sum_e base_emb[v][e] * Wx[e][j] ----------------
__global__ void k_xe(const float* __restrict__ base_emb, const float* __restrict__ Wx) {
    int v = blockIdx.x;        // 0..84
    int j = threadIdx.x;       // 0..255
    float s = 0.0f;
#pragma unroll
    for (int e = 0; e < 6; e++)
        s = fmaf(base_emb[v * 6 + e], Wx[e * 256 + j], s);
    g_xe[v * 256 + j] = s;
}

// ---------------- kernel 2: big sequence LSTM (from + to fused, shared weights) ----------------
// grid.x = 8192/8 = 1024 CTAs, 256 threads. Thread = one gate column j.
__global__ void __launch_bounds__(256, 2) k_seq(const int* __restrict__ from_seq,
                                                const int* __restrict__ to_seq,
                                                const float* __restrict__ Wh,
                                                const float* __restrict__ bias) {
    const int tid = threadIdx.x;
    const int row0 = blockIdx.x * 8;   // in [0, 8192)

    __shared__ alignas(16) float h_sh[8][64];
    __shared__ float g_sh[8][256];
    __shared__ int   tok[8][64];

    const int* seq = (row0 < BATCH) ? (from_seq + row0 * LSQ)
                                    : (to_seq + (row0 - BATCH) * LSQ);
    for (int i = tid; i < 8 * 64; i += 256) {
        tok[i >> 6][i & 63] = seq[i];
        h_sh[i >> 6][i & 63] = 0.0f;
    }

    // Wh column for this gate col, loaded once (coalesced across threads)
    float wcol[64];
#pragma unroll
    for (int k = 0; k < 64; k++) wcol[k] = Wh[k * 256 + tid];
    const float bj = bias[tid];

    // this thread owns cell (ur0, uh) and (ur1, uh) for the c/h update phase
    const int ur0 = tid >> 6;       // 0..3
    const int ur1 = ur0 + 4;        // 4..7
    const int uh = tid & 63;
    float c0 = 0.0f, c1 = 0.0f;

    __syncthreads();

    for (int t = 0; t < LSQ; t++) {
        // x-contribution: precomputed xe gather (L1-resident, coalesced within row)
        float xv[8];
#pragma unroll
        for (int r = 0; r < 8; r++) xv[r] = g_xe[tok[r][t] * 256 + tid];

        float acc[8];
#pragma unroll
        for (int r = 0; r < 8; r++) acc[r] = bj;

#pragma unroll
        for (int k4 = 0; k4 < 16; k4++) {
#pragma unroll
            for (int r = 0; r < 8; r++) {
                float4 hv = *reinterpret_cast<const float4*>(&h_sh[r][k4 * 4]);
                acc[r] = fmaf(hv.x, wcol[4 * k4 + 0], acc[r]);
                acc[r] = fmaf(hv.y, wcol[4 * k4 + 1], acc[r]);
                acc[r] = fmaf(hv.z, wcol[4 * k4 + 2], acc[r]);
                acc[r] = fmaf(hv.w, wcol[4 * k4 + 3], acc[r]);
            }
        }
#pragma unroll
        for (int r = 0; r < 8; r++) g_sh[r][tid] = acc[r] + xv[r];
        __syncthreads();   // gates ready; also guarantees h_sh reads above are done

        // update phase: 512 cells / 256 threads = 2 each. gate order i,f,g,o
        {
            float i0 = g_sh[ur0][uh],      f0 = g_sh[ur0][64 + uh];
            float gg0 = g_sh[ur0][128 + uh], o0 = g_sh[ur0][192 + uh];
            c0 = sigf(f0) * c0 + sigf(i0) * tanhf_fast(gg0);
            float h0 = sigf(o0) * tanhf_fast(c0);

            float i1 = g_sh[ur1][uh],      f1 = g_sh[ur1][64 + uh];
            float gg1 = g_sh[ur1][128 + uh], o1 = g_sh[ur1][192 + uh];
            c1 = sigf(f1) * c1 + sigf(i1) * tanhf_fast(gg1);
            float h1 = sigf(o1) * tanhf_fast(c1);

            h_sh[ur0][uh] = h0;
            h_sh[ur1][uh] = h1;
        }
        __syncthreads();   // h_sh stable for next step
    }

    for (int i = tid; i < 8 * 64; i += 256)
        g_m[row0 * 64 + i] = h_sh[i >> 6][i & 63];
}

// ---------------- kernel 3: 11 NWF list LSTMs (len 32, in 8, hid 8) ----------------
// grid = (4096/128, 11), 128 threads; one thread per (field,row).
__global__ void __launch_bounds__(128) k_nwf(const int* __restrict__ nums_g,
                                             const int* __restrict__ frs_g,
                                             const float* __restrict__ ne_g,
                                             const float* __restrict__ fe_g,
                                             const float* __restrict__ Wx_g,
                                             const float* __restrict__ Wh_g,
                                             const float* __restrict__ b_g) {
    const int tid = threadIdx.x;
    const int field = blockIdx.y;
    const int m = c_fm[field];

    __shared__ alignas(16) float wx[8 * 32];
    __shared__ alignas(16) float wh[8 * 32];
    __shared__ float bs[32];
    __shared__ int ns[32][132];   // transposed index strips, padded stride vs bank conflicts
    __shared__ int fs[32][132];

    for (int i = tid; i < 256; i += 128) {
        wx[i] = Wx_g[m * 256 + i];
        wh[i] = Wh_g[m * 256 + i];
    }
    if (tid < 32) bs[tid] = b_g[m * 32 + tid];

    const int base = field * BATCH * LN + blockIdx.x * 128 * LN;
    for (int i = tid; i < 128 * LN; i += 128) {
        int r = i >> 5, t = i & 31;
        ns[t][r] = nums_g[base + i];
        fs[t][r] = frs_g[base + i];
    }
    __syncthreads();

    const float4* neg = reinterpret_cast<const float4*>(ne_g) + m * 1000;  // [1000] float4
    const float4* feg = reinterpret_cast<const float4*>(fe_g) + m * 1000;

    float h[8], c[8];
#pragma unroll
    for (int k = 0; k < 8; k++) { h[k] = 0.0f; c[k] = 0.0f; }

    for (int t = 0; t < LN; t++) {
        float4 xn = __ldg(&neg[ns[t][tid]]);
        float4 xf = __ldg(&feg[fs[t][tid]]);
        float x[8] = {xn.x, xn.y, xn.z, xn.w, xf.x, xf.y, xf.z, xf.w};

        float acc[32];
#pragma unroll
        for (int j = 0; j < 32; j++) acc[j] = bs[j];

#pragma unroll
        for (int k = 0; k < 8; k++) {
#pragma unroll
            for (int j4 = 0; j4 < 8; j4++) {
                float4 w = *reinterpret_cast<const float4*>(&wx[k * 32 + j4 * 4]);
                acc[4 * j4 + 0] = fmaf(x[k], w.x, acc[4 * j4 + 0]);
                acc[4 * j4 + 1] = fmaf(x[k], w.y, acc[4 * j4 + 1]);
                acc[4 * j4 + 2] = fmaf(x[k], w.z, acc[4 * j4 + 2]);
                acc[4 * j4 + 3] = fmaf(x[k], w.w, acc[4 * j4 + 3]);
            }
        }
#pragma unroll
        for (int k = 0; k < 8; k++) {
#pragma unroll
            for (int j4 = 0; j4 < 8; j4++) {
                float4 w = *reinterpret_cast<const float4*>(&wh[k * 32 + j4 * 4]);
                acc[4 * j4 + 0] = fmaf(h[k], w.x, acc[4 * j4 + 0]);
                acc[4 * j4 + 1] = fmaf(h[k], w.y, acc[4 * j4 + 1]);
                acc[4 * j4 + 2] = fmaf(h[k], w.z, acc[4 * j4 + 2]);
                acc[4 * j4 + 3] = fmaf(h[k], w.w, acc[4 * j4 + 3]);
            }
        }
        // gates i=acc[0:8], f=acc[8:16], g=acc[16:24], o=acc[24:32]
#pragma unroll
        for (int k = 0; k < 8; k++) {
            c[k] = sigf(acc[8 + k]) * c[k] + sigf(acc[k]) * tanhf_fast(acc[16 + k]);
            h[k] = sigf(acc[24 + k]) * tanhf_fast(c[k]);
        }
    }

    const int row = blockIdx.x * 128 + tid;
    float* o = &g_nwf[(field * BATCH + row) * 8];
#pragma unroll
    for (int k = 0; k < 8; k++) o[k] = h[k];
}

// ---------------- kernel 4: feature concat + dense 234->64 + ReLU ----------------
// grid = 4096/8 = 512 blocks, 512 threads; thread = (row-in-tile, out-col)
__global__ void __launch_bounds__(512) k_final(const float* __restrict__ goby_emb,
                                               const float* __restrict__ bool_emb,
                                               const float* __restrict__ count_emb,
                                               const float* __restrict__ W,
                                               const float* __restrict__ bias,
                                               const int* __restrict__ goby_idx,
                                               const int* __restrict__ is_indel,
                                               const int* __restrict__ matches_ref,
                                               const int* __restrict__ count_fwd,
                                               const int* __restrict__ count_rev,
                                               float* __restrict__ out) {
    const int tid = threadIdx.x;
    const int row0 = blockIdx.x * 8;
    __shared__ float fsh[8][240];

    for (int i = tid; i < 8 * 234; i += 512) {
        int rr = i / 234, f = i % 234;
        int row = row0 + rr;
        float v;
        if (f < 4)        v = goby_emb[goby_idx[row] * 4 + f];
        else if (f < 6)   v = bool_emb[is_indel[row] * 2 + (f - 4)];
        else if (f < 8)   v = bool_emb[matches_ref[row] * 2 + (f - 6)];
        else if (f < 72)  v = g_m[row * 64 + (f - 8)];
        else if (f < 136) v = g_m[(BATCH + row) * 64 + (f - 72)];
        else if (f < 141) v = count_emb[count_fwd[row] * 5 + (f - 136)];
        else if (f < 146) v = count_emb[count_rev[row] * 5 + (f - 141)];
        else {
            int ff = f - 146;
            v = g_nwf[((ff >> 3) * BATCH + row) * 8 + (ff & 7)];
        }
        fsh[rr][f] = v;
    }
    __syncthreads();

    const int o = tid & 63;
    const int rr = tid >> 6;
    float acc = bias[o];
#pragma unroll 6
    for (int f = 0; f < 234; f++)
        acc = fmaf(fsh[rr][f], __ldg(&W[f * 64 + o]), acc);
    out[(row0 + rr) * 64 + o] = fmaxf(acc, 0.0f);
}

// ---------------- launch ----------------
extern "C" void kernel_launch(void* const* d_in, const int* in_sizes, int n_in,
                              void* d_out, int out_size) {
    // Input order detection:
    //   setup_inputs() dict order starts with goby_idx  (size 4096)
    //   reference-signature order starts with goby_emb (size 400)
    static const int dictmap[23]  = {0,1,2,3,4,5,6,7,8,9,10,11,12,13,14,15,16,17,18,19,20,21,22};
    static const int parammap[23] = {14,15,16,17,18,19,20,21,22,0,1,2,3,4,5,6,7,8,9,10,11,12,13};
    const int* mp = (in_sizes[0] == BATCH) ? dictmap : parammap;

    const int*   goby_idx     = (const int*)  d_in[mp[0]];
    const int*   is_indel     = (const int*)  d_in[mp[1]];
    const int*   matches_ref  = (const int*)  d_in[mp[2]];
    const int*   from_seq     = (const int*)  d_in[mp[3]];
    const int*   to_seq       = (const int*)  d_in[mp[4]];
    const int*   count_fwd    = (const int*)  d_in[mp[5]];
    const int*   count_rev    = (const int*)  d_in[mp[6]];
    const int*   nwf_numbers  = (const int*)  d_in[mp[7]];
    const int*   nwf_freqs    = (const int*)  d_in[mp[8]];
    const float* goby_emb     = (const float*)d_in[mp[9]];
    const float* bool_emb     = (const float*)d_in[mp[10]];
    const float* count_emb    = (const float*)d_in[mp[11]];
    const float* base_emb     = (const float*)d_in[mp[12]];
    const float* seq_Wx       = (const float*)d_in[mp[13]];
    const float* seq_Wh       = (const float*)d_in[mp[14]];
    const float* seq_b        = (const float*)d_in[mp[15]];
    const float* nwf_num_emb  = (const float*)d_in[mp[16]];
    const float* nwf_freq_emb = (const float*)d_in[mp[17]];
    const float* nwf_Wx       = (const float*)d_in[mp[18]];
    const float* nwf_Wh       = (const float*)d_in[mp[19]];
    const float* nwf_b        = (const float*)d_in[mp[20]];
    const float* reduce_W     = (const float*)d_in[mp[21]];
    const float* reduce_b     = (const float*)d_in[mp[22]];

    k_xe<<<85, 256>>>(base_emb, seq_Wx);
    k_nwf<<<dim3(BATCH / 128, NFLD), 128>>>(nwf_numbers, nwf_freqs,
                                            nwf_num_emb, nwf_freq_emb,
                                            nwf_Wx, nwf_Wh, nwf_b);
    k_seq<<<(2 * BATCH) / 8, 256>>>(from_seq, to_seq, seq_Wh, seq_b);
    k_final<<<BATCH / 8, 512>>>(goby_emb, bool_emb, count_emb, reduce_W, reduce_b,
                                goby_idx, is_indel, matches_ref, count_fwd, count_rev,
                                (float*)d_out);
}

// round 3
// speedup vs baseline: 1.6845x; 1.6845x over previous
#include <cuda_runtime.h>
#include <cuda_fp16.h>

#define BATCH 4096
#define LSQ   64
#define HID   64
#define NFLD  11
#define LN    32
#define SROWS 16   // rows per CTA in k_seq

// ---------------- scratch (no allocations allowed) ----------------
__device__ float g_xe[85 * 256];            // base_emb @ seq_Wx, per token value
__device__ float g_m[2 * BATCH * HID];      // [from rows 0..4095 | to rows 4096..8191] x 64
__device__ float g_nwf[NFLD * BATCH * 8];   // [11][4096][8]

__constant__ int c_fm[11] = {0, 0, 1, 1, 2, 2, 3, 3, 4, 5, 5};

__device__ __forceinline__ float sigf(float x) { return 1.0f / (1.0f + __expf(-x)); }
__device__ __forceinline__ float tanhf_fast(float x) { return 2.0f / (1.0f + __expf(-2.0f * x)) - 1.0f; }

// ---------------- kernel 1: xe[v][j] = sum_e base_emb[v][e] * Wx[e][j] ----------------
__global__ void k_xe(const float* __restrict__ base_emb, const float* __restrict__ Wx) {
    int v = blockIdx.x;        // 0..84
    int j = threadIdx.x;       // 0..255
    float s = 0.0f;
#pragma unroll
    for (int e = 0; e < 6; e++)
        s = fmaf(base_emb[v * 6 + e], Wx[e * 256 + j], s);
    g_xe[v * 256 + j] = s;
}

// ---------------- kernel 2: tensor-core sequence LSTM ----------------
// 16 rows/CTA, 256 threads (8 warps). Warp w owns gate columns [32w, 32w+32).
// Recurrence h@Wh on mma.sync.m16n8k16 with h split hi+lo fp16 (near-fp32 h),
// Wh rounded to fp16 once. x-path/bias/gates/output all fp32.
__global__ void __launch_bounds__(256, 2) k_seq(const int* __restrict__ from_seq,
                                                const int* __restrict__ to_seq,
                                                const float* __restrict__ Wh,
                                                const float* __restrict__ bias) {
    const int tid  = threadIdx.x;
    const int lane = tid & 31;
    const int w    = tid >> 5;
    const int gid  = lane >> 2;   // 0..7
    const int tig  = lane & 3;    // 0..3
    const int row0 = blockIdx.x * SROWS;   // in [0, 8192)

    __shared__ __half hhi[SROWS][72];      // padded stride vs LDSM bank conflicts
    __shared__ __half hlo[SROWS][72];
    __shared__ float  gsh[SROWS][264];     // gates fp32, padded stride (conflict-free)
    __shared__ int    tok[SROWS][LSQ];

    const int* seq = (row0 < BATCH) ? (from_seq + row0 * LSQ)
                                    : (to_seq + (row0 - BATCH) * LSQ);
    for (int i = tid; i < SROWS * LSQ; i += 256) tok[i >> 6][i & 63] = seq[i];
    for (int i = tid; i < SROWS * 72; i += 256) {
        hhi[i / 72][i % 72] = __float2half(0.0f);
        hlo[i / 72][i % 72] = __float2half(0.0f);
    }

    // --- persistent B fragments: Wh[k, col] fp16, m16n8k16 col-major B layout ---
    // bfr[kt][nt][0] = {Wh[k0][col], Wh[k0+1][col]}, [1] = rows k0+8,k0+9; col = 32w+8nt+gid
    unsigned bfr[4][4][2];
    const int colbase = 32 * w;
#pragma unroll
    for (int kt = 0; kt < 4; kt++)
#pragma unroll
        for (int nt = 0; nt < 4; nt++) {
            int col = colbase + 8 * nt + gid;
            int k0 = 16 * kt + 2 * tig;
            __half2 b0 = __floats2half2_rn(Wh[k0 * 256 + col], Wh[(k0 + 1) * 256 + col]);
            __half2 b1 = __floats2half2_rn(Wh[(k0 + 8) * 256 + col], Wh[(k0 + 9) * 256 + col]);
            bfr[kt][nt][0] = *reinterpret_cast<unsigned*>(&b0);
            bfr[kt][nt][1] = *reinterpret_cast<unsigned*>(&b1);
        }

    float2 bias2[4];
#pragma unroll
    for (int nt = 0; nt < 4; nt++) {
        int c0 = colbase + 8 * nt + 2 * tig;
        bias2[nt] = make_float2(bias[c0], bias[c0 + 1]);
    }

    // ldmatrix x4 source addresses for A tiles (16x16 at k-tile kt)
    const int arow = (lane < 16) ? lane : (lane - 16);
    const int acol = (lane < 16) ? 0 : 8;
    const unsigned hhib = (unsigned)__cvta_generic_to_shared(&hhi[arow][acol]);
    const unsigned hlob = (unsigned)__cvta_generic_to_shared(&hlo[arow][acol]);

    // update-phase ownership: thread owns 4 consecutive cells of one row
    const int ur  = tid >> 4;          // row 0..15
    const int uc0 = (tid & 15) * 4;    // hidden cols [uc0, uc0+4)
    float cst[4] = {0.0f, 0.0f, 0.0f, 0.0f};

    __syncthreads();

    for (int t = 0; t < LSQ; t++) {
        float d[4][4];
#pragma unroll
        for (int nt = 0; nt < 4; nt++)
#pragma unroll
            for (int q = 0; q < 4; q++) d[nt][q] = 0.0f;

#pragma unroll
        for (int kt = 0; kt < 4; kt++) {
            unsigned ah[4], al[4];
            asm volatile("ldmatrix.sync.aligned.m8n8.x4.shared.b16 {%0,%1,%2,%3}, [%4];\n"
                         : "=r"(ah[0]), "=r"(ah[1]), "=r"(ah[2]), "=r"(ah[3])
                         : "r"(hhib + kt * 32));
            asm volatile("ldmatrix.sync.aligned.m8n8.x4.shared.b16 {%0,%1,%2,%3}, [%4];\n"
                         : "=r"(al[0]), "=r"(al[1]), "=r"(al[2]), "=r"(al[3])
                         : "r"(hlob + kt * 32));
#pragma unroll
            for (int nt = 0; nt < 4; nt++) {
                asm volatile("mma.sync.aligned.m16n8k16.row.col.f32.f16.f16.f32 "
                             "{%0,%1,%2,%3},{%4,%5,%6,%7},{%8,%9},{%0,%1,%2,%3};\n"
                             : "+f"(d[nt][0]), "+f"(d[nt][1]), "+f"(d[nt][2]), "+f"(d[nt][3])
                             : "r"(ah[0]), "r"(ah[1]), "r"(ah[2]), "r"(ah[3]),
                               "r"(bfr[kt][nt][0]), "r"(bfr[kt][nt][1]));
                asm volatile("mma.sync.aligned.m16n8k16.row.col.f32.f16.f16.f32 "
                             "{%0,%1,%2,%3},{%4,%5,%6,%7},{%8,%9},{%0,%1,%2,%3};\n"
                             : "+f"(d[nt][0]), "+f"(d[nt][1]), "+f"(d[nt][2]), "+f"(d[nt][3])
                             : "r"(al[0]), "r"(al[1]), "r"(al[2]), "r"(al[3]),
                               "r"(bfr[kt][nt][0]), "r"(bfr[kt][nt][1]));
            }
        }

        // epilogue: gate = D + xe[token] + bias, fp32 into gsh
        const int tokA = tok[gid][t];
        const int tokB = tok[gid + 8][t];
#pragma unroll
        for (int nt = 0; nt < 4; nt++) {
            int c0 = colbase + 8 * nt + 2 * tig;
            float2 xa = *reinterpret_cast<const float2*>(&g_xe[tokA * 256 + c0]);
            float2 xb = *reinterpret_cast<const float2*>(&g_xe[tokB * 256 + c0]);
            float2 ga = make_float2(d[nt][0] + xa.x + bias2[nt].x,
                                    d[nt][1] + xa.y + bias2[nt].y);
            float2 gb = make_float2(d[nt][2] + xb.x + bias2[nt].x,
                                    d[nt][3] + xb.y + bias2[nt].y);
            *reinterpret_cast<float2*>(&gsh[gid][c0])     = ga;
            *reinterpret_cast<float2*>(&gsh[gid + 8][c0]) = gb;
        }
        __syncthreads();

        // update: 4 cells per thread, fp32 state; write h back as hi+lo fp16
        {
            float4 gi = *reinterpret_cast<const float4*>(&gsh[ur][uc0]);
            float4 gf = *reinterpret_cast<const float4*>(&gsh[ur][64 + uc0]);
            float4 gg = *reinterpret_cast<const float4*>(&gsh[ur][128 + uc0]);
            float4 go = *reinterpret_cast<const float4*>(&gsh[ur][192 + uc0]);
            float hv[4];
            const float gia[4] = {gi.x, gi.y, gi.z, gi.w};
            const float gfa[4] = {gf.x, gf.y, gf.z, gf.w};
            const float gga[4] = {gg.x, gg.y, gg.z, gg.w};
            const float goa[4] = {go.x, go.y, go.z, go.w};
#pragma unroll
            for (int q = 0; q < 4; q++) {
                cst[q] = sigf(gfa[q]) * cst[q] + sigf(gia[q]) * tanhf_fast(gga[q]);
                hv[q] = sigf(goa[q]) * tanhf_fast(cst[q]);
            }
            __half2 hi01 = __floats2half2_rn(hv[0], hv[1]);
            __half2 hi23 = __floats2half2_rn(hv[2], hv[3]);
            __half2 lo01 = __floats2half2_rn(hv[0] - __half2float(__low2half(hi01)),
                                             hv[1] - __half2float(__high2half(hi01)));
            __half2 lo23 = __floats2half2_rn(hv[2] - __half2float(__low2half(hi23)),
                                             hv[3] - __half2float(__high2half(hi23)));
            *reinterpret_cast<__half2*>(&hhi[ur][uc0])     = hi01;
            *reinterpret_cast<__half2*>(&hhi[ur][uc0 + 2]) = hi23;
            *reinterpret_cast<__half2*>(&hlo[ur][uc0])     = lo01;
            *reinterpret_cast<__half2*>(&hlo[ur][uc0 + 2]) = lo23;
            if (t == LSQ - 1) {
                *reinterpret_cast<float4*>(&g_m[(row0 + ur) * 64 + uc0]) =
                    make_float4(hv[0], hv[1], hv[2], hv[3]);
            }
        }
        __syncthreads();
    }
}

// ---------------- kernel 3: 11 NWF list LSTMs (len 32, in 8, hid 8) ----------------
__global__ void __launch_bounds__(128) k_nwf(const int* __restrict__ nums_g,
                                             const int* __restrict__ frs_g,
                                             const float* __restrict__ ne_g,
                                             const float* __restrict__ fe_g,
                                             const float* __restrict__ Wx_g,
                                             const float* __restrict__ Wh_g,
                                             const float* __restrict__ b_g) {
    const int tid = threadIdx.x;
    const int field = blockIdx.y;
    const int m = c_fm[field];

    __shared__ alignas(16) float wx[8 * 32];
    __shared__ alignas(16) float wh[8 * 32];
    __shared__ float bs[32];
    __shared__ int ns[32][132];
    __shared__ int fs[32][132];

    for (int i = tid; i < 256; i += 128) {
        wx[i] = Wx_g[m * 256 + i];
        wh[i] = Wh_g[m * 256 + i];
    }
    if (tid < 32) bs[tid] = b_g[m * 32 + tid];

    const int base = field * BATCH * LN + blockIdx.x * 128 * LN;
    for (int i = tid; i < 128 * LN; i += 128) {
        int r = i >> 5, t = i & 31;
        ns[t][r] = nums_g[base + i];
        fs[t][r] = frs_g[base + i];
    }
    __syncthreads();

    const float4* neg = reinterpret_cast<const float4*>(ne_g) + m * 1000;
    const float4* feg = reinterpret_cast<const float4*>(fe_g) + m * 1000;

    float h[8], c[8];
#pragma unroll
    for (int k = 0; k < 8; k++) { h[k] = 0.0f; c[k] = 0.0f; }

    for (int t = 0; t < LN; t++) {
        float4 xn = __ldg(&neg[ns[t][tid]]);
        float4 xf = __ldg(&feg[fs[t][tid]]);
        float x[8] = {xn.x, xn.y, xn.z, xn.w, xf.x, xf.y, xf.z, xf.w};

        float acc[32];
#pragma unroll
        for (int j = 0; j < 32; j++) acc[j] = bs[j];

#pragma unroll
        for (int k = 0; k < 8; k++) {
#pragma unroll
            for (int j4 = 0; j4 < 8; j4++) {
                float4 wv = *reinterpret_cast<const float4*>(&wx[k * 32 + j4 * 4]);
                acc[4 * j4 + 0] = fmaf(x[k], wv.x, acc[4 * j4 + 0]);
                acc[4 * j4 + 1] = fmaf(x[k], wv.y, acc[4 * j4 + 1]);
                acc[4 * j4 + 2] = fmaf(x[k], wv.z, acc[4 * j4 + 2]);
                acc[4 * j4 + 3] = fmaf(x[k], wv.w, acc[4 * j4 + 3]);
            }
        }
#pragma unroll
        for (int k = 0; k < 8; k++) {
#pragma unroll
            for (int j4 = 0; j4 < 8; j4++) {
                float4 wv = *reinterpret_cast<const float4*>(&wh[k * 32 + j4 * 4]);
                acc[4 * j4 + 0] = fmaf(h[k], wv.x, acc[4 * j4 + 0]);
                acc[4 * j4 + 1] = fmaf(h[k], wv.y, acc[4 * j4 + 1]);
                acc[4 * j4 + 2] = fmaf(h[k], wv.z, acc[4 * j4 + 2]);
                acc[4 * j4 + 3] = fmaf(h[k], wv.w, acc[4 * j4 + 3]);
            }
        }
#pragma unroll
        for (int k = 0; k < 8; k++) {
            c[k] = sigf(acc[8 + k]) * c[k] + sigf(acc[k]) * tanhf_fast(acc[16 + k]);
            h[k] = sigf(acc[24 + k]) * tanhf_fast(c[k]);
        }
    }

    const int row = blockIdx.x * 128 + tid;
    float* o = &g_nwf[(field * BATCH + row) * 8];
#pragma unroll
    for (int k = 0; k < 8; k++) o[k] = h[k];
}

// ---------------- kernel 4: feature concat + dense 234->64 + ReLU ----------------
__global__ void __launch_bounds__(512) k_final(const float* __restrict__ goby_emb,
                                               const float* __restrict__ bool_emb,
                                               const float* __restrict__ count_emb,
                                               const float* __restrict__ W,
                                               const float* __restrict__ bias,
                                               const int* __restrict__ goby_idx,
                                               const int* __restrict__ is_indel,
                                               const int* __restrict__ matches_ref,
                                               const int* __restrict__ count_fwd,
                                               const int* __restrict__ count_rev,
                                               float* __restrict__ out) {
    const int tid = threadIdx.x;
    const int row0 = blockIdx.x * 8;
    __shared__ float fsh[8][240];

    for (int i = tid; i < 8 * 234; i += 512) {
        int rr = i / 234, f = i % 234;
        int row = row0 + rr;
        float v;
        if (f < 4)        v = goby_emb[goby_idx[row] * 4 + f];
        else if (f < 6)   v = bool_emb[is_indel[row] * 2 + (f - 4)];
        else if (f < 8)   v = bool_emb[matches_ref[row] * 2 + (f - 6)];
        else if (f < 72)  v = g_m[row * 64 + (f - 8)];
        else if (f < 136) v = g_m[(BATCH + row) * 64 + (f - 72)];
        else if (f < 141) v = count_emb[count_fwd[row] * 5 + (f - 136)];
        else if (f < 146) v = count_emb[count_rev[row] * 5 + (f - 141)];
        else {
            int ff = f - 146;
            v = g_nwf[((ff >> 3) * BATCH + row) * 8 + (ff & 7)];
        }
        fsh[rr][f] = v;
    }
    __syncthreads();

    const int o = tid & 63;
    const int rr = tid >> 6;
    float acc = bias[o];
#pragma unroll 6
    for (int f = 0; f < 234; f++)
        acc = fmaf(fsh[rr][f], __ldg(&W[f * 64 + o]), acc);
    out[(row0 + rr) * 64 + o] = fmaxf(acc, 0.0f);
}

// ---------------- launch ----------------
extern "C" void kernel_launch(void* const* d_in, const int* in_sizes, int n_in,
                              void* d_out, int out_size) {
    static const int dictmap[23]  = {0,1,2,3,4,5,6,7,8,9,10,11,12,13,14,15,16,17,18,19,20,21,22};
    static const int parammap[23] = {14,15,16,17,18,19,20,21,22,0,1,2,3,4,5,6,7,8,9,10,11,12,13};
    const int* mp = (in_sizes[0] == BATCH) ? dictmap : parammap;

    const int*   goby_idx     = (const int*)  d_in[mp[0]];
    const int*   is_indel     = (const int*)  d_in[mp[1]];
    const int*   matches_ref  = (const int*)  d_in[mp[2]];
    const int*   from_seq     = (const int*)  d_in[mp[3]];
    const int*   to_seq       = (const int*)  d_in[mp[4]];
    const int*   count_fwd    = (const int*)  d_in[mp[5]];
    const int*   count_rev    = (const int*)  d_in[mp[6]];
    const int*   nwf_numbers  = (const int*)  d_in[mp[7]];
    const int*   nwf_freqs    = (const int*)  d_in[mp[8]];
    const float* goby_emb     = (const float*)d_in[mp[9]];
    const float* bool_emb     = (const float*)d_in[mp[10]];
    const float* count_emb    = (const float*)d_in[mp[11]];
    const float* base_emb     = (const float*)d_in[mp[12]];
    const float* seq_Wx       = (const float*)d_in[mp[13]];
    const float* seq_Wh       = (const float*)d_in[mp[14]];
    const float* seq_b        = (const float*)d_in[mp[15]];
    const float* nwf_num_emb  = (const float*)d_in[mp[16]];
    const float* nwf_freq_emb = (const float*)d_in[mp[17]];
    const float* nwf_Wx       = (const float*)d_in[mp[18]];
    const float* nwf_Wh       = (const float*)d_in[mp[19]];
    const float* nwf_b        = (const float*)d_in[mp[20]];
    const float* reduce_W     = (const float*)d_in[mp[21]];
    const float* reduce_b     = (const float*)d_in[mp[22]];

    k_xe<<<85, 256>>>(base_emb, seq_Wx);
    k_seq<<<(2 * BATCH) / SROWS, 256>>>(from_seq, to_seq, seq_Wh, seq_b);
    k_nwf<<<dim3(BATCH / 128, NFLD), 128>>>(nwf_numbers, nwf_freqs,
                                            nwf_num_emb, nwf_freq_emb,
                                            nwf_Wx, nwf_Wh, nwf_b);
    k_final<<<BATCH / 8, 512>>>(goby_emb, bool_emb, count_emb, reduce_W, reduce_b,
                                goby_idx, is_indel, matches_ref, count_fwd, count_rev,
                                (float*)d_out);
}

// round 4
// speedup vs baseline: 1.8780x; 1.1149x over previous
#include <cuda_runtime.h>
#include <cuda_fp16.h>

#define BATCH 4096
#define LSQ   64
#define HID   64
#define NFLD  11
#define LN    32
#define SROWS 16   // rows per CTA in k_seq

// ---------------- scratch (no allocations allowed) ----------------
__device__ float g_xe[85 * 256];            // base_emb @ seq_Wx, per token value
__device__ float g_m[2 * BATCH * HID];      // [from rows 0..4095 | to rows 4096..8191] x 64
__device__ float g_nwf[NFLD * BATCH * 8];   // [11][4096][8]

__constant__ int c_fm[11] = {0, 0, 1, 1, 2, 2, 3, 3, 4, 5, 5};

__device__ __forceinline__ float sigf(float x) { return 1.0f / (1.0f + __expf(-x)); }
__device__ __forceinline__ float tanhf_fast(float x) { return 2.0f / (1.0f + __expf(-2.0f * x)) - 1.0f; }

// ---------------- kernel 1: xe[v][j] = sum_e base_emb[v][e] * Wx[e][j] ----------------
__global__ void k_xe(const float* __restrict__ base_emb, const float* __restrict__ Wx) {
    int v = blockIdx.x;        // 0..84
    int j = threadIdx.x;       // 0..255
    float s = 0.0f;
#pragma unroll
    for (int e = 0; e < 6; e++)
        s = fmaf(base_emb[v * 6 + e], Wx[e * 256 + j], s);
    g_xe[v * 256 + j] = s;
}

// ---------------- kernel 2: tensor-core sequence LSTM, gate-local layout ----------------
// 16 rows/CTA, 256 threads (8 warps). Warp w owns hidden columns [8w, 8w+8) and
// computes ALL FOUR gate tiles for them (N-tiles at cols 64g+8w, g=0..3).
// => thread (gid,tig) holds i,f,g,o of its own 4 cells in registers; update is
// fully local. h kept as single fp16 (Wh fp16), ping-pong h buffer, 1 sync/step.
__global__ void __launch_bounds__(256, 3) k_seq(const int* __restrict__ from_seq,
                                                const int* __restrict__ to_seq,
                                                const float* __restrict__ Wh,
                                                const float* __restrict__ bias) {
    const int tid  = threadIdx.x;
    const int lane = tid & 31;
    const int w    = tid >> 5;    // warp 0..7 -> hidden cols [8w, 8w+8)
    const int gid  = lane >> 2;   // 0..7
    const int tig  = lane & 3;    // 0..3
    const int row0 = blockIdx.x * SROWS;   // in [0, 8192)

    __shared__ __half hbuf[2][SROWS][72];  // ping-pong, padded stride (LDSM conflict-free)
    __shared__ int    tok[SROWS][LSQ];

    const int* seq = (row0 < BATCH) ? (from_seq + row0 * LSQ)
                                    : (to_seq + (row0 - BATCH) * LSQ);
    for (int i = tid; i < SROWS * LSQ; i += 256) tok[i >> 6][i & 63] = seq[i];
    for (int i = tid; i < 2 * SROWS * 72; i += 256)
        (&hbuf[0][0][0])[i] = __float2half(0.0f);

    // --- persistent B fragments (m16n8k16.row.col): gate g, k-tile kt ---
    // col = 64g + 8w + gid ; reg0 = Wh[16kt+2tig+{0,1}][col], reg1 = rows +8,+9
    unsigned bfr[4][4][2];
#pragma unroll
    for (int g = 0; g < 4; g++)
#pragma unroll
        for (int kt = 0; kt < 4; kt++) {
            int col = 64 * g + 8 * w + gid;
            int k0 = 16 * kt + 2 * tig;
            __half2 b0 = __floats2half2_rn(Wh[k0 * 256 + col], Wh[(k0 + 1) * 256 + col]);
            __half2 b1 = __floats2half2_rn(Wh[(k0 + 8) * 256 + col], Wh[(k0 + 9) * 256 + col]);
            bfr[g][kt][0] = *reinterpret_cast<unsigned*>(&b0);
            bfr[g][kt][1] = *reinterpret_cast<unsigned*>(&b1);
        }

    const int hc0 = 8 * w + 2 * tig;      // this thread's hidden col pair
    float2 b2[4];
#pragma unroll
    for (int g = 0; g < 4; g++)
        b2[g] = make_float2(bias[64 * g + hc0], bias[64 * g + hc0 + 1]);

    // ldmatrix x4 source addressing (16x16 A tile at k-tile kt)
    const int arow = (lane < 16) ? lane : (lane - 16);
    const int acol = (lane < 16) ? 0 : 8;
    const unsigned hb0 = (unsigned)__cvta_generic_to_shared(&hbuf[0][arow][acol]);
    const unsigned hb1 = (unsigned)__cvta_generic_to_shared(&hbuf[1][arow][acol]);

    float cst[4] = {0.0f, 0.0f, 0.0f, 0.0f};   // cells: (gid,hc0),(gid,hc0+1),(gid+8,hc0),(gid+8,hc0+1)

    __syncthreads();

    for (int t = 0; t < LSQ; t++) {
        const unsigned hrd = (t & 1) ? hb1 : hb0;

        float d[4][4];
#pragma unroll
        for (int g = 0; g < 4; g++)
#pragma unroll
            for (int q = 0; q < 4; q++) d[g][q] = 0.0f;

#pragma unroll
        for (int kt = 0; kt < 4; kt++) {
            unsigned ah[4];
            asm volatile("ldmatrix.sync.aligned.m8n8.x4.shared.b16 {%0,%1,%2,%3}, [%4];\n"
                         : "=r"(ah[0]), "=r"(ah[1]), "=r"(ah[2]), "=r"(ah[3])
                         : "r"(hrd + kt * 32));
#pragma unroll
            for (int g = 0; g < 4; g++) {
                asm volatile("mma.sync.aligned.m16n8k16.row.col.f32.f16.f16.f32 "
                             "{%0,%1,%2,%3},{%4,%5,%6,%7},{%8,%9},{%0,%1,%2,%3};\n"
                             : "+f"(d[g][0]), "+f"(d[g][1]), "+f"(d[g][2]), "+f"(d[g][3])
                             : "r"(ah[0]), "r"(ah[1]), "r"(ah[2]), "r"(ah[3]),
                               "r"(bfr[g][kt][0]), "r"(bfr[g][kt][1]));
            }
        }

        // gates for the thread's own 4 cells (all in registers)
        const int tokA = tok[gid][t];
        const int tokB = tok[gid + 8][t];
        float2 xa[4], xb[4];
#pragma unroll
        for (int g = 0; g < 4; g++) {
            xa[g] = *reinterpret_cast<const float2*>(&g_xe[tokA * 256 + 64 * g + hc0]);
            xb[g] = *reinterpret_cast<const float2*>(&g_xe[tokB * 256 + 64 * g + hc0]);
        }

        float hv[4];
        {   // cell 0: (rowA, hc0)
            float gi = d[0][0] + xa[0].x + b2[0].x;
            float gf = d[1][0] + xa[1].x + b2[1].x;
            float gg = d[2][0] + xa[2].x + b2[2].x;
            float go = d[3][0] + xa[3].x + b2[3].x;
            cst[0] = sigf(gf) * cst[0] + sigf(gi) * tanhf_fast(gg);
            hv[0] = sigf(go) * tanhf_fast(cst[0]);
        }
        {   // cell 1: (rowA, hc0+1)
            float gi = d[0][1] + xa[0].y + b2[0].y;
            float gf = d[1][1] + xa[1].y + b2[1].y;
            float gg = d[2][1] + xa[2].y + b2[2].y;
            float go = d[3][1] + xa[3].y + b2[3].y;
            cst[1] = sigf(gf) * cst[1] + sigf(gi) * tanhf_fast(gg);
            hv[1] = sigf(go) * tanhf_fast(cst[1]);
        }
        {   // cell 2: (rowB, hc0)
            float gi = d[0][2] + xb[0].x + b2[0].x;
            float gf = d[1][2] + xb[1].x + b2[1].x;
            float gg = d[2][2] + xb[2].x + b2[2].x;
            float go = d[3][2] + xb[3].x + b2[3].x;
            cst[2] = sigf(gf) * cst[2] + sigf(gi) * tanhf_fast(gg);
            hv[2] = sigf(go) * tanhf_fast(cst[2]);
        }
        {   // cell 3: (rowB, hc0+1)
            float gi = d[0][3] + xb[0].y + b2[0].y;
            float gf = d[1][3] + xb[1].y + b2[1].y;
            float gg = d[2][3] + xb[2].y + b2[2].y;
            float go = d[3][3] + xb[3].y + b2[3].y;
            cst[3] = sigf(gf) * cst[3] + sigf(gi) * tanhf_fast(gg);
            hv[3] = sigf(go) * tanhf_fast(cst[3]);
        }

        // write h (fp16) into the other buffer; conflict-free pattern
        const int wb = (t & 1) ^ 1;
        *reinterpret_cast<__half2*>(&hbuf[wb][gid][hc0])     = __floats2half2_rn(hv[0], hv[1]);
        *reinterpret_cast<__half2*>(&hbuf[wb][gid + 8][hc0]) = __floats2half2_rn(hv[2], hv[3]);

        if (t == LSQ - 1) {
            *reinterpret_cast<float2*>(&g_m[(row0 + gid) * 64 + hc0])     = make_float2(hv[0], hv[1]);
            *reinterpret_cast<float2*>(&g_m[(row0 + gid + 8) * 64 + hc0]) = make_float2(hv[2], hv[3]);
        }
        __syncthreads();
    }
}

// ---------------- kernel 3: 11 NWF list LSTMs (len 32, in 8, hid 8) ----------------
__global__ void __launch_bounds__(128) k_nwf(const int* __restrict__ nums_g,
                                             const int* __restrict__ frs_g,
                                             const float* __restrict__ ne_g,
                                             const float* __restrict__ fe_g,
                                             const float* __restrict__ Wx_g,
                                             const float* __restrict__ Wh_g,
                                             const float* __restrict__ b_g) {
    const int tid = threadIdx.x;
    const int field = blockIdx.y;
    const int m = c_fm[field];

    __shared__ alignas(16) float wx[8 * 32];
    __shared__ alignas(16) float wh[8 * 32];
    __shared__ float bs[32];
    __shared__ int ns[32][132];
    __shared__ int fs[32][132];

    for (int i = tid; i < 256; i += 128) {
        wx[i] = Wx_g[m * 256 + i];
        wh[i] = Wh_g[m * 256 + i];
    }
    if (tid < 32) bs[tid] = b_g[m * 32 + tid];

    const int base = field * BATCH * LN + blockIdx.x * 128 * LN;
    for (int i = tid; i < 128 * LN; i += 128) {
        int r = i >> 5, t = i & 31;
        ns[t][r] = nums_g[base + i];
        fs[t][r] = frs_g[base + i];
    }
    __syncthreads();

    const float4* neg = reinterpret_cast<const float4*>(ne_g) + m * 1000;
    const float4* feg = reinterpret_cast<const float4*>(fe_g) + m * 1000;

    float h[8], c[8];
#pragma unroll
    for (int k = 0; k < 8; k++) { h[k] = 0.0f; c[k] = 0.0f; }

    for (int t = 0; t < LN; t++) {
        float4 xn = __ldg(&neg[ns[t][tid]]);
        float4 xf = __ldg(&feg[fs[t][tid]]);
        float x[8] = {xn.x, xn.y, xn.z, xn.w, xf.x, xf.y, xf.z, xf.w};

        float acc[32];
#pragma unroll
        for (int j = 0; j < 32; j++) acc[j] = bs[j];

#pragma unroll
        for (int k = 0; k < 8; k++) {
#pragma unroll
            for (int j4 = 0; j4 < 8; j4++) {
                float4 wv = *reinterpret_cast<const float4*>(&wx[k * 32 + j4 * 4]);
                acc[4 * j4 + 0] = fmaf(x[k], wv.x, acc[4 * j4 + 0]);
                acc[4 * j4 + 1] = fmaf(x[k], wv.y, acc[4 * j4 + 1]);
                acc[4 * j4 + 2] = fmaf(x[k], wv.z, acc[4 * j4 + 2]);
                acc[4 * j4 + 3] = fmaf(x[k], wv.w, acc[4 * j4 + 3]);
            }
        }
#pragma unroll
        for (int k = 0; k < 8; k++) {
#pragma unroll
            for (int j4 = 0; j4 < 8; j4++) {
                float4 wv = *reinterpret_cast<const float4*>(&wh[k * 32 + j4 * 4]);
                acc[4 * j4 + 0] = fmaf(h[k], wv.x, acc[4 * j4 + 0]);
                acc[4 * j4 + 1] = fmaf(h[k], wv.y, acc[4 * j4 + 1]);
                acc[4 * j4 + 2] = fmaf(h[k], wv.z, acc[4 * j4 + 2]);
                acc[4 * j4 + 3] = fmaf(h[k], wv.w, acc[4 * j4 + 3]);
            }
        }
#pragma unroll
        for (int k = 0; k < 8; k++) {
            c[k] = sigf(acc[8 + k]) * c[k] + sigf(acc[k]) * tanhf_fast(acc[16 + k]);
            h[k] = sigf(acc[24 + k]) * tanhf_fast(c[k]);
        }
    }

    const int row = blockIdx.x * 128 + tid;
    float* o = &g_nwf[(field * BATCH + row) * 8];
#pragma unroll
    for (int k = 0; k < 8; k++) o[k] = h[k];
}

// ---------------- kernel 4: feature concat + dense 234->64 + ReLU ----------------
__global__ void __launch_bounds__(512) k_final(const float* __restrict__ goby_emb,
                                               const float* __restrict__ bool_emb,
                                               const float* __restrict__ count_emb,
                                               const float* __restrict__ W,
                                               const float* __restrict__ bias,
                                               const int* __restrict__ goby_idx,
                                               const int* __restrict__ is_indel,
                                               const int* __restrict__ matches_ref,
                                               const int* __restrict__ count_fwd,
                                               const int* __restrict__ count_rev,
                                               float* __restrict__ out) {
    const int tid = threadIdx.x;
    const int row0 = blockIdx.x * 8;
    __shared__ float fsh[8][240];

    for (int i = tid; i < 8 * 234; i += 512) {
        int rr = i / 234, f = i % 234;
        int row = row0 + rr;
        float v;
        if (f < 4)        v = goby_emb[goby_idx[row] * 4 + f];
        else if (f < 6)   v = bool_emb[is_indel[row] * 2 + (f - 4)];
        else if (f < 8)   v = bool_emb[matches_ref[row] * 2 + (f - 6)];
        else if (f < 72)  v = g_m[row * 64 + (f - 8)];
        else if (f < 136) v = g_m[(BATCH + row) * 64 + (f - 72)];
        else if (f < 141) v = count_emb[count_fwd[row] * 5 + (f - 136)];
        else if (f < 146) v = count_emb[count_rev[row] * 5 + (f - 141)];
        else {
            int ff = f - 146;
            v = g_nwf[((ff >> 3) * BATCH + row) * 8 + (ff & 7)];
        }
        fsh[rr][f] = v;
    }
    __syncthreads();

    const int o = tid & 63;
    const int rr = tid >> 6;
    float acc = bias[o];
#pragma unroll 6
    for (int f = 0; f < 234; f++)
        acc = fmaf(fsh[rr][f], __ldg(&W[f * 64 + o]), acc);
    out[(row0 + rr) * 64 + o] = fmaxf(acc, 0.0f);
}

// ---------------- launch ----------------
extern "C" void kernel_launch(void* const* d_in, const int* in_sizes, int n_in,
                              void* d_out, int out_size) {
    static const int dictmap[23]  = {0,1,2,3,4,5,6,7,8,9,10,11,12,13,14,15,16,17,18,19,20,21,22};
    static const int parammap[23] = {14,15,16,17,18,19,20,21,22,0,1,2,3,4,5,6,7,8,9,10,11,12,13};
    const int* mp = (in_sizes[0] == BATCH) ? dictmap : parammap;

    const int*   goby_idx     = (const int*)  d_in[mp[0]];
    const int*   is_indel     = (const int*)  d_in[mp[1]];
    const int*   matches_ref  = (const int*)  d_in[mp[2]];
    const int*   from_seq     = (const int*)  d_in[mp[3]];
    const int*   to_seq       = (const int*)  d_in[mp[4]];
    const int*   count_fwd    = (const int*)  d_in[mp[5]];
    const int*   count_rev    = (const int*)  d_in[mp[6]];
    const int*   nwf_numbers  = (const int*)  d_in[mp[7]];
    const int*   nwf_freqs    = (const int*)  d_in[mp[8]];
    const float* goby_emb     = (const float*)d_in[mp[9]];
    const float* bool_emb     = (const float*)d_in[mp[10]];
    const float* count_emb    = (const float*)d_in[mp[11]];
    const float* base_emb     = (const float*)d_in[mp[12]];
    const float* seq_Wx       = (const float*)d_in[mp[13]];
    const float* seq_Wh       = (const float*)d_in[mp[14]];
    const float* seq_b        = (const float*)d_in[mp[15]];
    const float* nwf_num_emb  = (const float*)d_in[mp[16]];
    const float* nwf_freq_emb = (const float*)d_in[mp[17]];
    const float* nwf_Wx       = (const float*)d_in[mp[18]];
    const float* nwf_Wh       = (const float*)d_in[mp[19]];
    const float* nwf_b        = (const float*)d_in[mp[20]];
    const float* reduce_W     = (const float*)d_in[mp[21]];
    const float* reduce_b     = (const float*)d_in[mp[22]];

    k_xe<<<85, 256>>>(base_emb, seq_Wx);
    k_seq<<<(2 * BATCH) / SROWS, 256>>>(from_seq, to_seq, seq_Wh, seq_b);
    k_nwf<<<dim3(BATCH / 128, NFLD), 128>>>(nwf_numbers, nwf_freqs,
                                            nwf_num_emb, nwf_freq_emb,
                                            nwf_Wx, nwf_Wh, nwf_b);
    k_final<<<BATCH / 8, 512>>>(goby_emb, bool_emb, count_emb, reduce_W, reduce_b,
                                goby_idx, is_indel, matches_ref, count_fwd, count_rev,
                                (float*)d_out);
}

// round 5
// speedup vs baseline: 1.9396x; 1.0328x over previous
#include <cuda_runtime.h>
#include <cuda_fp16.h>

#define BATCH 4096
#define LSQ   64
#define HID   64
#define NFLD  11
#define LN    32
#define SROWS 16   // rows per CTA in k_seq

// ---------------- scratch (no allocations allowed) ----------------
__device__ float g_xe[85 * 256];            // base_emb @ seq_Wx + bias, per token value
__device__ float g_m[2 * BATCH * HID];      // [from rows 0..4095 | to rows 4096..8191] x 64
__device__ float g_nwf[NFLD * BATCH * 8];   // [11][4096][8]

__constant__ int c_fm[11] = {0, 0, 1, 1, 2, 2, 3, 3, 4, 5, 5};

__device__ __forceinline__ float sigf(float x) { return 1.0f / (1.0f + __expf(-x)); }
__device__ __forceinline__ float tanhf_fast(float x) { return 2.0f / (1.0f + __expf(-2.0f * x)) - 1.0f; }

// ---------------- kernel 1: xe[v][j] = sum_e base_emb[v][e] * Wx[e][j] + bias[j] ----------------
__global__ void k_xe(const float* __restrict__ base_emb, const float* __restrict__ Wx,
                     const float* __restrict__ bias) {
    int v = blockIdx.x;        // 0..84
    int j = threadIdx.x;       // 0..255
    float s = bias[j];
#pragma unroll
    for (int e = 0; e < 6; e++)
        s = fmaf(base_emb[v * 6 + e], Wx[e * 256 + j], s);
    g_xe[v * 256 + j] = s;
}

// ---------------- kernel 2: tensor-core sequence LSTM, gate-local layout ----------------
// 16 rows/CTA, 256 threads (8 warps). Warp w owns hidden columns [8w, 8w+8) and
// computes ALL FOUR gate tiles for them. Thread-local i,f,g,o -> register update.
// occ 2 (128-reg budget: no spills). Bias pre-folded into g_xe.
__global__ void __launch_bounds__(256, 2) k_seq(const int* __restrict__ from_seq,
                                                const int* __restrict__ to_seq,
                                                const float* __restrict__ Wh) {
    const int tid  = threadIdx.x;
    const int lane = tid & 31;
    const int w    = tid >> 5;    // warp 0..7 -> hidden cols [8w, 8w+8)
    const int gid  = lane >> 2;   // 0..7
    const int tig  = lane & 3;    // 0..3
    const int row0 = blockIdx.x * SROWS;   // in [0, 8192)

    __shared__ __half hbuf[2][SROWS][72];  // ping-pong, padded stride (LDSM conflict-free)
    __shared__ int    tok[SROWS][LSQ];

    const int* seq = (row0 < BATCH) ? (from_seq + row0 * LSQ)
                                    : (to_seq + (row0 - BATCH) * LSQ);
    for (int i = tid; i < SROWS * LSQ; i += 256) tok[i >> 6][i & 63] = seq[i];
    for (int i = tid; i < 2 * SROWS * 72; i += 256)
        (&hbuf[0][0][0])[i] = __float2half(0.0f);

    // --- persistent B fragments (m16n8k16.row.col): gate g, k-tile kt ---
    unsigned bfr[4][4][2];
#pragma unroll
    for (int g = 0; g < 4; g++)
#pragma unroll
        for (int kt = 0; kt < 4; kt++) {
            int col = 64 * g + 8 * w + gid;
            int k0 = 16 * kt + 2 * tig;
            __half2 b0 = __floats2half2_rn(Wh[k0 * 256 + col], Wh[(k0 + 1) * 256 + col]);
            __half2 b1 = __floats2half2_rn(Wh[(k0 + 8) * 256 + col], Wh[(k0 + 9) * 256 + col]);
            bfr[g][kt][0] = *reinterpret_cast<unsigned*>(&b0);
            bfr[g][kt][1] = *reinterpret_cast<unsigned*>(&b1);
        }

    const int hc0 = 8 * w + 2 * tig;      // this thread's hidden col pair

    // ldmatrix x4 source addressing (16x16 A tile at k-tile kt)
    const int arow = (lane < 16) ? lane : (lane - 16);
    const int acol = (lane < 16) ? 0 : 8;
    const unsigned hb0 = (unsigned)__cvta_generic_to_shared(&hbuf[0][arow][acol]);
    const unsigned hb1 = (unsigned)__cvta_generic_to_shared(&hbuf[1][arow][acol]);

    float cst[4] = {0.0f, 0.0f, 0.0f, 0.0f};

    __syncthreads();

    for (int t = 0; t < LSQ; t++) {
        const unsigned hrd = (t & 1) ? hb1 : hb0;

        // x-gather first: LDG latency overlaps the LDSM+MMA block below
        const int tokA = tok[gid][t];
        const int tokB = tok[gid + 8][t];
        float2 xa[4], xb[4];
#pragma unroll
        for (int g = 0; g < 4; g++) {
            xa[g] = *reinterpret_cast<const float2*>(&g_xe[tokA * 256 + 64 * g + hc0]);
            xb[g] = *reinterpret_cast<const float2*>(&g_xe[tokB * 256 + 64 * g + hc0]);
        }

        float d[4][4];
#pragma unroll
        for (int g = 0; g < 4; g++)
#pragma unroll
            for (int q = 0; q < 4; q++) d[g][q] = 0.0f;

#pragma unroll
        for (int kt = 0; kt < 4; kt++) {
            unsigned ah[4];
            asm volatile("ldmatrix.sync.aligned.m8n8.x4.shared.b16 {%0,%1,%2,%3}, [%4];\n"
                         : "=r"(ah[0]), "=r"(ah[1]), "=r"(ah[2]), "=r"(ah[3])
                         : "r"(hrd + kt * 32));
#pragma unroll
            for (int g = 0; g < 4; g++) {
                asm("mma.sync.aligned.m16n8k16.row.col.f32.f16.f16.f32 "
                    "{%0,%1,%2,%3},{%4,%5,%6,%7},{%8,%9},{%0,%1,%2,%3};\n"
                    : "+f"(d[g][0]), "+f"(d[g][1]), "+f"(d[g][2]), "+f"(d[g][3])
                    : "r"(ah[0]), "r"(ah[1]), "r"(ah[2]), "r"(ah[3]),
                      "r"(bfr[g][kt][0]), "r"(bfr[g][kt][1]));
            }
        }

        float hv[4];
        {   // cell 0: (rowA, hc0)
            float gi = d[0][0] + xa[0].x;
            float gf = d[1][0] + xa[1].x;
            float gg = d[2][0] + xa[2].x;
            float go = d[3][0] + xa[3].x;
            cst[0] = sigf(gf) * cst[0] + sigf(gi) * tanhf_fast(gg);
            hv[0] = sigf(go) * tanhf_fast(cst[0]);
        }
        {   // cell 1: (rowA, hc0+1)
            float gi = d[0][1] + xa[0].y;
            float gf = d[1][1] + xa[1].y;
            float gg = d[2][1] + xa[2].y;
            float go = d[3][1] + xa[3].y;
            cst[1] = sigf(gf) * cst[1] + sigf(gi) * tanhf_fast(gg);
            hv[1] = sigf(go) * tanhf_fast(cst[1]);
        }
        {   // cell 2: (rowB, hc0)
            float gi = d[0][2] + xb[0].x;
            float gf = d[1][2] + xb[1].x;
            float gg = d[2][2] + xb[2].x;
            float go = d[3][2] + xb[3].x;
            cst[2] = sigf(gf) * cst[2] + sigf(gi) * tanhf_fast(gg);
            hv[2] = sigf(go) * tanhf_fast(cst[2]);
        }
        {   // cell 3: (rowB, hc0+1)
            float gi = d[0][3] + xb[0].y;
            float gf = d[1][3] + xb[1].y;
            float gg = d[2][3] + xb[2].y;
            float go = d[3][3] + xb[3].y;
            cst[3] = sigf(gf) * cst[3] + sigf(gi) * tanhf_fast(gg);
            hv[3] = sigf(go) * tanhf_fast(cst[3]);
        }

        const int wb = (t & 1) ^ 1;
        *reinterpret_cast<__half2*>(&hbuf[wb][gid][hc0])     = __floats2half2_rn(hv[0], hv[1]);
        *reinterpret_cast<__half2*>(&hbuf[wb][gid + 8][hc0]) = __floats2half2_rn(hv[2], hv[3]);

        if (t == LSQ - 1) {
            *reinterpret_cast<float2*>(&g_m[(row0 + gid) * 64 + hc0])     = make_float2(hv[0], hv[1]);
            *reinterpret_cast<float2*>(&g_m[(row0 + gid + 8) * 64 + hc0]) = make_float2(hv[2], hv[3]);
        }
        __syncthreads();
    }
}

// ---------------- kernel 3: 11 NWF list LSTMs (len 32, in 8, hid 8) ----------------
__global__ void __launch_bounds__(128) k_nwf(const int* __restrict__ nums_g,
                                             const int* __restrict__ frs_g,
                                             const float* __restrict__ ne_g,
                                             const float* __restrict__ fe_g,
                                             const float* __restrict__ Wx_g,
                                             const float* __restrict__ Wh_g,
                                             const float* __restrict__ b_g) {
    const int tid = threadIdx.x;
    const int field = blockIdx.y;
    const int m = c_fm[field];

    __shared__ alignas(16) float wx[8 * 32];
    __shared__ alignas(16) float wh[8 * 32];
    __shared__ float bs[32];
    __shared__ int ns[32][132];
    __shared__ int fs[32][132];

    for (int i = tid; i < 256; i += 128) {
        wx[i] = Wx_g[m * 256 + i];
        wh[i] = Wh_g[m * 256 + i];
    }
    if (tid < 32) bs[tid] = b_g[m * 32 + tid];

    const int base = field * BATCH * LN + blockIdx.x * 128 * LN;
    for (int i = tid; i < 128 * LN; i += 128) {
        int r = i >> 5, t = i & 31;
        ns[t][r] = nums_g[base + i];
        fs[t][r] = frs_g[base + i];
    }
    __syncthreads();

    const float4* neg = reinterpret_cast<const float4*>(ne_g) + m * 1000;
    const float4* feg = reinterpret_cast<const float4*>(fe_g) + m * 1000;

    float h[8], c[8];
#pragma unroll
    for (int k = 0; k < 8; k++) { h[k] = 0.0f; c[k] = 0.0f; }

    for (int t = 0; t < LN; t++) {
        float4 xn = __ldg(&neg[ns[t][tid]]);
        float4 xf = __ldg(&feg[fs[t][tid]]);
        float x[8] = {xn.x, xn.y, xn.z, xn.w, xf.x, xf.y, xf.z, xf.w};

        float acc[32];
#pragma unroll
        for (int j = 0; j < 32; j++) acc[j] = bs[j];

#pragma unroll
        for (int k = 0; k < 8; k++) {
#pragma unroll
            for (int j4 = 0; j4 < 8; j4++) {
                float4 wv = *reinterpret_cast<const float4*>(&wx[k * 32 + j4 * 4]);
                acc[4 * j4 + 0] = fmaf(x[k], wv.x, acc[4 * j4 + 0]);
                acc[4 * j4 + 1] = fmaf(x[k], wv.y, acc[4 * j4 + 1]);
                acc[4 * j4 + 2] = fmaf(x[k], wv.z, acc[4 * j4 + 2]);
                acc[4 * j4 + 3] = fmaf(x[k], wv.w, acc[4 * j4 + 3]);
            }
        }
#pragma unroll
        for (int k = 0; k < 8; k++) {
#pragma unroll
            for (int j4 = 0; j4 < 8; j4++) {
                float4 wv = *reinterpret_cast<const float4*>(&wh[k * 32 + j4 * 4]);
                acc[4 * j4 + 0] = fmaf(h[k], wv.x, acc[4 * j4 + 0]);
                acc[4 * j4 + 1] = fmaf(h[k], wv.y, acc[4 * j4 + 1]);
                acc[4 * j4 + 2] = fmaf(h[k], wv.z, acc[4 * j4 + 2]);
                acc[4 * j4 + 3] = fmaf(h[k], wv.w, acc[4 * j4 + 3]);
            }
        }
#pragma unroll
        for (int k = 0; k < 8; k++) {
            c[k] = sigf(acc[8 + k]) * c[k] + sigf(acc[k]) * tanhf_fast(acc[16 + k]);
            h[k] = sigf(acc[24 + k]) * tanhf_fast(c[k]);
        }
    }

    const int row = blockIdx.x * 128 + tid;
    float* o = &g_nwf[(field * BATCH + row) * 8];
#pragma unroll
    for (int k = 0; k < 8; k++) o[k] = h[k];
}

// ---------------- kernel 4: feature concat + dense 234->64 + ReLU ----------------
__global__ void __launch_bounds__(512) k_final(const float* __restrict__ goby_emb,
                                               const float* __restrict__ bool_emb,
                                               const float* __restrict__ count_emb,
                                               const float* __restrict__ W,
                                               const float* __restrict__ bias,
                                               const int* __restrict__ goby_idx,
                                               const int* __restrict__ is_indel,
                                               const int* __restrict__ matches_ref,
                                               const int* __restrict__ count_fwd,
                                               const int* __restrict__ count_rev,
                                               float* __restrict__ out) {
    const int tid = threadIdx.x;
    const int row0 = blockIdx.x * 8;
    __shared__ float fsh[8][240];

    for (int i = tid; i < 8 * 234; i += 512) {
        int rr = i / 234, f = i % 234;
        int row = row0 + rr;
        float v;
        if (f < 4)        v = goby_emb[goby_idx[row] * 4 + f];
        else if (f < 6)   v = bool_emb[is_indel[row] * 2 + (f - 4)];
        else if (f < 8)   v = bool_emb[matches_ref[row] * 2 + (f - 6)];
        else if (f < 72)  v = g_m[row * 64 + (f - 8)];
        else if (f < 136) v = g_m[(BATCH + row) * 64 + (f - 72)];
        else if (f < 141) v = count_emb[count_fwd[row] * 5 + (f - 136)];
        else if (f < 146) v = count_emb[count_rev[row] * 5 + (f - 141)];
        else {
            int ff = f - 146;
            v = g_nwf[((ff >> 3) * BATCH + row) * 8 + (ff & 7)];
        }
        fsh[rr][f] = v;
    }
    __syncthreads();

    const int o = tid & 63;
    const int rr = tid >> 6;
    float acc = bias[o];
#pragma unroll 6
    for (int f = 0; f < 234; f++)
        acc = fmaf(fsh[rr][f], __ldg(&W[f * 64 + o]), acc);
    out[(row0 + rr) * 64 + o] = fmaxf(acc, 0.0f);
}

// ---------------- launch ----------------
extern "C" void kernel_launch(void* const* d_in, const int* in_sizes, int n_in,
                              void* d_out, int out_size) {
    static const int dictmap[23]  = {0,1,2,3,4,5,6,7,8,9,10,11,12,13,14,15,16,17,18,19,20,21,22};
    static const int parammap[23] = {14,15,16,17,18,19,20,21,22,0,1,2,3,4,5,6,7,8,9,10,11,12,13};
    const int* mp = (in_sizes[0] == BATCH) ? dictmap : parammap;

    const int*   goby_idx     = (const int*)  d_in[mp[0]];
    const int*   is_indel     = (const int*)  d_in[mp[1]];
    const int*   matches_ref  = (const int*)  d_in[mp[2]];
    const int*   from_seq     = (const int*)  d_in[mp[3]];
    const int*   to_seq       = (const int*)  d_in[mp[4]];
    const int*   count_fwd    = (const int*)  d_in[mp[5]];
    const int*   count_rev    = (const int*)  d_in[mp[6]];
    const int*   nwf_numbers  = (const int*)  d_in[mp[7]];
    const int*   nwf_freqs    = (const int*)  d_in[mp[8]];
    const float* goby_emb     = (const float*)d_in[mp[9]];
    const float* bool_emb     = (const float*)d_in[mp[10]];
    const float* count_emb    = (const float*)d_in[mp[11]];
    const float* base_emb     = (const float*)d_in[mp[12]];
    const float* seq_Wx       = (const float*)d_in[mp[13]];
    const float* seq_Wh       = (const float*)d_in[mp[14]];
    const float* seq_b        = (const float*)d_in[mp[15]];
    const float* nwf_num_emb  = (const float*)d_in[mp[16]];
    const float* nwf_freq_emb = (const float*)d_in[mp[17]];
    const float* nwf_Wx       = (const float*)d_in[mp[18]];
    const float* nwf_Wh       = (const float*)d_in[mp[19]];
    const float* nwf_b        = (const float*)d_in[mp[20]];
    const float* reduce_W     = (const float*)d_in[mp[21]];
    const float* reduce_b     = (const float*)d_in[mp[22]];

    k_xe<<<85, 256>>>(base_emb, seq_Wx, seq_b);
    k_seq<<<(2 * BATCH) / SROWS, 256>>>(from_seq, to_seq, seq_Wh);
    k_nwf<<<dim3(BATCH / 128, NFLD), 128>>>(nwf_numbers, nwf_freqs,
                                            nwf_num_emb, nwf_freq_emb,
                                            nwf_Wx, nwf_Wh, nwf_b);
    k_final<<<BATCH / 8, 512>>>(goby_emb, bool_emb, count_emb, reduce_W, reduce_b,
                                goby_idx, is_indel, matches_ref, count_fwd, count_rev,
                                (float*)d_out);
}

// round 6
// speedup vs baseline: 4.7454x; 2.4466x over previous
#include <cuda_runtime.h>
#include <cuda_fp16.h>

#define BATCH 4096
#define LSQ   64
#define HID   64
#define NFLD  11
#define LN    32
#define SROWS 16   // rows per CTA in k_seq

// ---------------- scratch (no allocations allowed) ----------------
__device__ float g_m[2 * BATCH * HID];      // [from rows 0..4095 | to rows 4096..8191] x 64
__device__ float g_nwf[NFLD * BATCH * 8];   // [11][4096][8]

__constant__ int c_fm[11] = {0, 0, 1, 1, 2, 2, 3, 3, 4, 5, 5};

__device__ __forceinline__ float tanh_hw(float x) {
    float y; asm("tanh.approx.f32 %0, %1;" : "=f"(y) : "f"(x)); return y;
}
__device__ __forceinline__ float sig_hw(float x) {
    return fmaf(tanh_hw(0.5f * x), 0.5f, 0.5f);
}

// ---------------- kernel 1: tensor-core sequence LSTM, x folded into MMA ----------------
// gates = [h(64) | emb(tok)(6) | 1 | 0...] @ [Wh ; Wx ; bias ; 0]  -> K=80, 5 k-tiles.
// 16 rows/CTA, 256 threads (8 warps). Warp w owns hidden cols [8w,8w+8), all 4 gates.
// Epilogue is pure activation; h ping-pong fp16; tanh.approx activations.
__global__ void __launch_bounds__(256, 3) k_seq(const int* __restrict__ from_seq,
                                                const int* __restrict__ to_seq,
                                                const float* __restrict__ Wh,
                                                const float* __restrict__ Wx,
                                                const float* __restrict__ bias,
                                                const float* __restrict__ base_emb) {
    const int tid  = threadIdx.x;
    const int lane = tid & 31;
    const int w    = tid >> 5;    // warp 0..7 -> hidden cols [8w, 8w+8)
    const int gid  = lane >> 2;   // 0..7
    const int tig  = lane & 3;    // 0..3
    const int row0 = blockIdx.x * SROWS;   // in [0, 8192)

    __shared__ __half  hbuf[2][SROWS][88]; // cols 0-63 h, 64-69 emb, 70 = 1.0, 71-79 = 0
    __shared__ int     tok[SROWS][LSQ];
    __shared__ __half2 ebase[85][3];       // base_emb fp16, 3 half2 per vocab entry

    const int* seq = (row0 < BATCH) ? (from_seq + row0 * LSQ)
                                    : (to_seq + (row0 - BATCH) * LSQ);
    for (int i = tid; i < SROWS * LSQ; i += 256) tok[i >> 6][i & 63] = seq[i];
    for (int i = tid; i < 2 * SROWS * 88; i += 256)
        (&hbuf[0][0][0])[i] = __float2half(0.0f);
    for (int i = tid; i < 85 * 3; i += 256) {
        int v = i / 3, p = i % 3;
        ebase[v][p] = __floats2half2_rn(base_emb[v * 6 + 2 * p], base_emb[v * 6 + 2 * p + 1]);
    }
    __syncthreads();
    // specials: constant-1 column (both buffers), emb(tok_0) in buffer 0
    if (tid < 32) hbuf[tid >> 4][tid & 15][70] = __float2half(1.0f);
    if (tid < 48) {
        int r = tid / 3, p = tid % 3;
        *reinterpret_cast<__half2*>(&hbuf[0][r][64 + 2 * p]) = ebase[tok[r][0]][p];
    }

    // --- persistent B fragments (m16n8k16.row.col): gate g, k-tile kt (kt=4 = Wx|bias|0) ---
    unsigned bfr[4][5][2];
#pragma unroll
    for (int g = 0; g < 4; g++) {
        const int col = 64 * g + 8 * w + gid;
#pragma unroll
        for (int kt = 0; kt < 4; kt++) {
            int k0 = 16 * kt + 2 * tig;
            __half2 b0 = __floats2half2_rn(Wh[k0 * 256 + col], Wh[(k0 + 1) * 256 + col]);
            __half2 b1 = __floats2half2_rn(Wh[(k0 + 8) * 256 + col], Wh[(k0 + 9) * 256 + col]);
            bfr[g][kt][0] = *reinterpret_cast<unsigned*>(&b0);
            bfr[g][kt][1] = *reinterpret_cast<unsigned*>(&b1);
        }
        {   // kt=4: K rows 64..79 -> 64-69 Wx, 70 bias, 71-79 zero
            int r0 = 64 + 2 * tig;
            float v0 = (r0 < 70) ? Wx[(r0 - 64) * 256 + col] : ((r0 == 70) ? bias[col] : 0.0f);
            float v1 = (r0 + 1 < 70) ? Wx[(r0 - 63) * 256 + col] : ((r0 + 1 == 70) ? bias[col] : 0.0f);
            __half2 b0 = __floats2half2_rn(v0, v1);
            bfr[g][4][0] = *reinterpret_cast<unsigned*>(&b0);
            bfr[g][4][1] = 0u;   // rows 72..79 all zero
        }
    }

    const int hc0 = 8 * w + 2 * tig;      // this thread's hidden col pair

    // ldmatrix x4 source addressing (16x16 A tile at k-tile kt)
    const int arow = (lane < 16) ? lane : (lane - 16);
    const int acol = (lane < 16) ? 0 : 8;
    const unsigned hb0 = (unsigned)__cvta_generic_to_shared(&hbuf[0][arow][acol]);
    const unsigned hb1 = (unsigned)__cvta_generic_to_shared(&hbuf[1][arow][acol]);

    float cst[4] = {0.0f, 0.0f, 0.0f, 0.0f};

    __syncthreads();

    for (int t = 0; t < LSQ; t++) {
        const unsigned hrd = (t & 1) ? hb1 : hb0;

        float d[4][4];
#pragma unroll
        for (int g = 0; g < 4; g++)
#pragma unroll
            for (int q = 0; q < 4; q++) d[g][q] = 0.0f;

#pragma unroll
        for (int kt = 0; kt < 5; kt++) {
            unsigned ah[4];
            asm volatile("ldmatrix.sync.aligned.m8n8.x4.shared.b16 {%0,%1,%2,%3}, [%4];\n"
                         : "=r"(ah[0]), "=r"(ah[1]), "=r"(ah[2]), "=r"(ah[3])
                         : "r"(hrd + kt * 32));
#pragma unroll
            for (int g = 0; g < 4; g++) {
                asm("mma.sync.aligned.m16n8k16.row.col.f32.f16.f16.f32 "
                    "{%0,%1,%2,%3},{%4,%5,%6,%7},{%8,%9},{%0,%1,%2,%3};\n"
                    : "+f"(d[g][0]), "+f"(d[g][1]), "+f"(d[g][2]), "+f"(d[g][3])
                    : "r"(ah[0]), "r"(ah[1]), "r"(ah[2]), "r"(ah[3]),
                      "r"(bfr[g][kt][0]), "r"(bfr[g][kt][1]));
            }
        }

        // d[g][q] are the complete gate pre-activations (x + bias inside MMA)
        float hv[4];
#pragma unroll
        for (int q = 0; q < 4; q++) {
            cst[q] = sig_hw(d[1][q]) * cst[q] + sig_hw(d[0][q]) * tanh_hw(d[2][q]);
            hv[q]  = sig_hw(d[3][q]) * tanh_hw(cst[q]);
        }

        const int wb = (t & 1) ^ 1;
        *reinterpret_cast<__half2*>(&hbuf[wb][gid][hc0])     = __floats2half2_rn(hv[0], hv[1]);
        *reinterpret_cast<__half2*>(&hbuf[wb][gid + 8][hc0]) = __floats2half2_rn(hv[2], hv[3]);
        if (t < LSQ - 1 && tid < 48) {
            int r = tid / 3, p = tid % 3;
            *reinterpret_cast<__half2*>(&hbuf[wb][r][64 + 2 * p]) = ebase[tok[r][t + 1]][p];
        }

        if (t == LSQ - 1) {
            *reinterpret_cast<float2*>(&g_m[(row0 + gid) * 64 + hc0])     = make_float2(hv[0], hv[1]);
            *reinterpret_cast<float2*>(&g_m[(row0 + gid + 8) * 64 + hc0]) = make_float2(hv[2], hv[3]);
        }
        __syncthreads();
    }
}

// ---------------- kernel 2: 11 NWF list LSTMs (len 32, in 8, hid 8) ----------------
__global__ void __launch_bounds__(128) k_nwf(const int* __restrict__ nums_g,
                                             const int* __restrict__ frs_g,
                                             const float* __restrict__ ne_g,
                                             const float* __restrict__ fe_g,
                                             const float* __restrict__ Wx_g,
                                             const float* __restrict__ Wh_g,
                                             const float* __restrict__ b_g) {
    const int tid = threadIdx.x;
    const int field = blockIdx.y;
    const int m = c_fm[field];

    __shared__ alignas(16) float wx[8 * 32];
    __shared__ alignas(16) float wh[8 * 32];
    __shared__ float bs[32];
    __shared__ int ns[32][132];
    __shared__ int fs[32][132];

    for (int i = tid; i < 256; i += 128) {
        wx[i] = Wx_g[m * 256 + i];
        wh[i] = Wh_g[m * 256 + i];
    }
    if (tid < 32) bs[tid] = b_g[m * 32 + tid];

    const int base = field * BATCH * LN + blockIdx.x * 128 * LN;
    for (int i = tid; i < 128 * LN; i += 128) {
        int r = i >> 5, t = i & 31;
        ns[t][r] = nums_g[base + i];
        fs[t][r] = frs_g[base + i];
    }
    __syncthreads();

    const float4* neg = reinterpret_cast<const float4*>(ne_g) + m * 1000;
    const float4* feg = reinterpret_cast<const float4*>(fe_g) + m * 1000;

    float h[8], c[8];
#pragma unroll
    for (int k = 0; k < 8; k++) { h[k] = 0.0f; c[k] = 0.0f; }

    for (int t = 0; t < LN; t++) {
        float4 xn = __ldg(&neg[ns[t][tid]]);
        float4 xf = __ldg(&feg[fs[t][tid]]);
        float x[8] = {xn.x, xn.y, xn.z, xn.w, xf.x, xf.y, xf.z, xf.w};

        float acc[32];
#pragma unroll
        for (int j = 0; j < 32; j++) acc[j] = bs[j];

#pragma unroll
        for (int k = 0; k < 8; k++) {
#pragma unroll
            for (int j4 = 0; j4 < 8; j4++) {
                float4 wv = *reinterpret_cast<const float4*>(&wx[k * 32 + j4 * 4]);
                acc[4 * j4 + 0] = fmaf(x[k], wv.x, acc[4 * j4 + 0]);
                acc[4 * j4 + 1] = fmaf(x[k], wv.y, acc[4 * j4 + 1]);
                acc[4 * j4 + 2] = fmaf(x[k], wv.z, acc[4 * j4 + 2]);
                acc[4 * j4 + 3] = fmaf(x[k], wv.w, acc[4 * j4 + 3]);
            }
        }
#pragma unroll
        for (int k = 0; k < 8; k++) {
#pragma unroll
            for (int j4 = 0; j4 < 8; j4++) {
                float4 wv = *reinterpret_cast<const float4*>(&wh[k * 32 + j4 * 4]);
                acc[4 * j4 + 0] = fmaf(h[k], wv.x, acc[4 * j4 + 0]);
                acc[4 * j4 + 1] = fmaf(h[k], wv.y, acc[4 * j4 + 1]);
                acc[4 * j4 + 2] = fmaf(h[k], wv.z, acc[4 * j4 + 2]);
                acc[4 * j4 + 3] = fmaf(h[k], wv.w, acc[4 * j4 + 3]);
            }
        }
#pragma unroll
        for (int k = 0; k < 8; k++) {
            c[k] = sig_hw(acc[8 + k]) * c[k] + sig_hw(acc[k]) * tanh_hw(acc[16 + k]);
            h[k] = sig_hw(acc[24 + k]) * tanh_hw(c[k]);
        }
    }

    const int row = blockIdx.x * 128 + tid;
    float* o = &g_nwf[(field * BATCH + row) * 8];
#pragma unroll
    for (int k = 0; k < 8; k++) o[k] = h[k];
}

// ---------------- kernel 3: feature concat + dense 234->64 + ReLU ----------------
__global__ void __launch_bounds__(512) k_final(const float* __restrict__ goby_emb,
                                               const float* __restrict__ bool_emb,
                                               const float* __restrict__ count_emb,
                                               const float* __restrict__ W,
                                               const float* __restrict__ bias,
                                               const int* __restrict__ goby_idx,
                                               const int* __restrict__ is_indel,
                                               const int* __restrict__ matches_ref,
                                               const int* __restrict__ count_fwd,
                                               const int* __restrict__ count_rev,
                                               float* __restrict__ out) {
    const int tid = threadIdx.x;
    const int row0 = blockIdx.x * 8;
    __shared__ float fsh[8][240];

    for (int i = tid; i < 8 * 234; i += 512) {
        int rr = i / 234, f = i % 234;
        int row = row0 + rr;
        float v;
        if (f < 4)        v = goby_emb[goby_idx[row] * 4 + f];
        else if (f < 6)   v = bool_emb[is_indel[row] * 2 + (f - 4)];
        else if (f < 8)   v = bool_emb[matches_ref[row] * 2 + (f - 6)];
        else if (f < 72)  v = g_m[row * 64 + (f - 8)];
        else if (f < 136) v = g_m[(BATCH + row) * 64 + (f - 72)];
        else if (f < 141) v = count_emb[count_fwd[row] * 5 + (f - 136)];
        else if (f < 146) v = count_emb[count_rev[row] * 5 + (f - 141)];
        else {
            int ff = f - 146;
            v = g_nwf[((ff >> 3) * BATCH + row) * 8 + (ff & 7)];
        }
        fsh[rr][f] = v;
    }
    __syncthreads();

    const int o = tid & 63;
    const int rr = tid >> 6;
    float acc = bias[o];
#pragma unroll 6
    for (int f = 0; f < 234; f++)
        acc = fmaf(fsh[rr][f], __ldg(&W[f * 64 + o]), acc);
    out[(row0 + rr) * 64 + o] = fmaxf(acc, 0.0f);
}

// ---------------- launch ----------------
extern "C" void kernel_launch(void* const* d_in, const int* in_sizes, int n_in,
                              void* d_out, int out_size) {
    static const int dictmap[23]  = {0,1,2,3,4,5,6,7,8,9,10,11,12,13,14,15,16,17,18,19,20,21,22};
    static const int parammap[23] = {14,15,16,17,18,19,20,21,22,0,1,2,3,4,5,6,7,8,9,10,11,12,13};
    const int* mp = (in_sizes[0] == BATCH) ? dictmap : parammap;

    const int*   goby_idx     = (const int*)  d_in[mp[0]];
    const int*   is_indel     = (const int*)  d_in[mp[1]];
    const int*   matches_ref  = (const int*)  d_in[mp[2]];
    const int*   from_seq     = (const int*)  d_in[mp[3]];
    const int*   to_seq       = (const int*)  d_in[mp[4]];
    const int*   count_fwd    = (const int*)  d_in[mp[5]];
    const int*   count_rev    = (const int*)  d_in[mp[6]];
    const int*   nwf_numbers  = (const int*)  d_in[mp[7]];
    const int*   nwf_freqs    = (const int*)  d_in[mp[8]];
    const float* goby_emb     = (const float*)d_in[mp[9]];
    const float* bool_emb     = (const float*)d_in[mp[10]];
    const float* count_emb    = (const float*)d_in[mp[11]];
    const float* base_emb     = (const float*)d_in[mp[12]];
    const float* seq_Wx       = (const float*)d_in[mp[13]];
    const float* seq_Wh       = (const float*)d_in[mp[14]];
    const float* seq_b        = (const float*)d_in[mp[15]];
    const float* nwf_num_emb  = (const float*)d_in[mp[16]];
    const float* nwf_freq_emb = (const float*)d_in[mp[17]];
    const float* nwf_Wx       = (const float*)d_in[mp[18]];
    const float* nwf_Wh       = (const float*)d_in[mp[19]];
    const float* nwf_b        = (const float*)d_in[mp[20]];
    const float* reduce_W     = (const float*)d_in[mp[21]];
    const float* reduce_b     = (const float*)d_in[mp[22]];

    k_seq<<<(2 * BATCH) / SROWS, 256>>>(from_seq, to_seq, seq_Wh, seq_Wx, seq_b, base_emb);
    k_nwf<<<dim3(BATCH / 128, NFLD), 128>>>(nwf_numbers, nwf_freqs,
                                            nwf_num_emb, nwf_freq_emb,
                                            nwf_Wx, nwf_Wh, nwf_b);
    k_final<<<BATCH / 8, 512>>>(goby_emb, bool_emb, count_emb, reduce_W, reduce_b,
                                goby_idx, is_indel, matches_ref, count_fwd, count_rev,
                                (float*)d_out);
}